// round 3
// baseline (speedup 1.0000x reference)
#include <cuda_runtime.h>

#define BQ 64
#define NQ 64
#define TQ 4096
#define BN (BQ * NQ)   // 4096 floats per time slice

// Scratch (module-load allocated): E = exp(emissions) in [t][b][j] layout,
// plus linear-domain alpha/beta (arbitrary per-(b,t) scale; cancels in gamma).
__device__ float g_E[TQ * BN];
__device__ float g_alpha[TQ * BN];
__device__ float g_beta[TQ * BN];

// ---------------------------------------------------------------------------
// Kernel 1: E[t][b][j] = exp(emissions[b][j][t])  (tiled transpose via shared)
// grid (T/64, B), 256 threads
// ---------------------------------------------------------------------------
__global__ void __launch_bounds__(256) expT_kernel(const float* __restrict__ em) {
    __shared__ float tile[64][65];
    int b  = blockIdx.y;
    int t0 = blockIdx.x * 64;
    int tid = threadIdx.x;
    int c  = tid & 63;   // fast index
    int r4 = tid >> 6;   // 0..3

#pragma unroll
    for (int rep = 0; rep < 16; rep++) {
        int j = rep * 4 + r4;
        tile[j][c] = __expf(em[b * NQ * TQ + j * TQ + t0 + c]);
    }
    __syncthreads();
#pragma unroll
    for (int rep = 0; rep < 16; rep++) {
        int tt = rep * 4 + r4;
        g_E[(t0 + tt) * BN + b * NQ + c] = tile[c][tt];
    }
}

// ---------------------------------------------------------------------------
// Kernel 2: forward/backward linear-domain scans.
// grid (B, 2): blockIdx.x = batch, blockIdx.y = 0 fwd / 1 bwd. 64 threads.
// Thread j holds column j (fwd) or row j (bwd) of A in 64 registers.
// Renormalize by the vector sum every 8 steps (uniform scale cancels in gamma).
// ---------------------------------------------------------------------------
__global__ void __launch_bounds__(64) scan_kernel(const float* __restrict__ trans,
                                                 const float* __restrict__ init) {
    const int b    = blockIdx.x;
    const int dir  = blockIdx.y;
    const int j    = threadIdx.x;
    const int lane = j & 31;
    const int w    = j >> 5;

    __shared__ __align__(16) float psh[2][64];
    __shared__ float red[2];

    float A0[32], A1[32];   // 64 matrix values per thread, split even/odd
    if (dir == 0) {
        // column j of A: A0[k] = A[2k][j], A1[k] = A[2k+1][j]
#pragma unroll
        for (int k = 0; k < 32; k++) {
            A0[k] = trans[(2 * k) * NQ + j];
            A1[k] = trans[(2 * k + 1) * NQ + j];
        }
    } else {
        // row j of A (contiguous)
        const float2* row = (const float2*)(trans + j * NQ);
#pragma unroll
        for (int k = 0; k < 32; k++) {
            float2 p = row[k];
            A0[k] = p.x;
            A1[k] = p.y;
        }
    }

    const int base = b * NQ + j;
    float eb[4];  // E prefetch pipeline, depth 4

    if (dir == 0) {
        // ---------------- forward ----------------
        float v = init[j] * g_E[0 * BN + base];
        {   // normalize at t=0
            float s = v;
#pragma unroll
            for (int o = 16; o; o >>= 1) s += __shfl_xor_sync(0xffffffffu, s, o);
            if (lane == 0) red[w] = s;
            __syncthreads();
            s = red[0] + red[1];
            v *= (1.0f / s);
        }
        psh[0][j] = v;
        g_alpha[0 * BN + base] = v;

        // prefill E pipeline for t = 1..4
        eb[1 & 3] = g_E[1 * BN + base];
        eb[2 & 3] = g_E[2 * BN + base];
        eb[3 & 3] = g_E[3 * BN + base];
        eb[4 & 3] = g_E[4 * BN + base];
        __syncthreads();

        for (int t = 1; t < TQ; t++) {
            float e_cur = eb[t & 3];
            int tp = t + 4 < TQ ? t + 4 : TQ - 1;
            eb[t & 3] = g_E[tp * BN + base];   // prefetch 4 ahead

            const float4* pv = (const float4*)&psh[(t - 1) & 1][0];
            float s0 = 0.f, s1 = 0.f, s2 = 0.f, s3 = 0.f;
#pragma unroll
            for (int k = 0; k < 16; k++) {
                float4 q = pv[k];
                s0 = fmaf(q.x, A0[2 * k],     s0);
                s1 = fmaf(q.y, A1[2 * k],     s1);
                s2 = fmaf(q.z, A0[2 * k + 1], s2);
                s3 = fmaf(q.w, A1[2 * k + 1], s3);
            }
            float v2 = ((s0 + s1) + (s2 + s3)) * e_cur;

            if ((t & 7) == 7) {   // periodic renorm (keeps fp32 in range)
                float s = v2;
#pragma unroll
                for (int o = 16; o; o >>= 1) s += __shfl_xor_sync(0xffffffffu, s, o);
                if (lane == 0) red[w] = s;
                __syncthreads();
                s = red[0] + red[1];
                v2 *= (1.0f / s);
            }
            psh[t & 1][j] = v2;
            g_alpha[t * BN + base] = v2;
            __syncthreads();
        }
    } else {
        // ---------------- backward ----------------
        float e_T = g_E[(TQ - 1) * BN + base];
        g_beta[(TQ - 1) * BN + base] = 1.0f;
        psh[(TQ - 1) & 1][j] = e_T;    // carry = beta_{T-1} * E_{T-1}

        float e_t = g_E[(TQ - 2) * BN + base];   // E_t for first computed step
        // prefill pipeline with E for upcoming steps
        eb[(TQ - 3) & 3] = g_E[(TQ - 3) * BN + base];
        eb[(TQ - 4) & 3] = g_E[(TQ - 4) * BN + base];
        eb[(TQ - 5) & 3] = g_E[(TQ - 5) * BN + base];
        eb[(TQ - 6) & 3] = g_E[(TQ - 6) * BN + base];
        __syncthreads();

        for (int t = TQ - 2; t >= 0; t--) {
            int tp = t - 5 >= 0 ? t - 5 : 0;
            float e_pref = g_E[tp * BN + base];   // prefetch (rotates in below)

            const float4* pv = (const float4*)&psh[(t + 1) & 1][0];
            float s0 = 0.f, s1 = 0.f, s2 = 0.f, s3 = 0.f;
#pragma unroll
            for (int k = 0; k < 16; k++) {
                float4 q = pv[k];
                s0 = fmaf(q.x, A0[2 * k],     s0);
                s1 = fmaf(q.y, A1[2 * k],     s1);
                s2 = fmaf(q.z, A0[2 * k + 1], s2);
                s3 = fmaf(q.w, A1[2 * k + 1], s3);
            }
            float v2 = (s0 + s1) + (s2 + s3);

            if ((t & 7) == 0) {
                float s = v2;
#pragma unroll
                for (int o = 16; o; o >>= 1) s += __shfl_xor_sync(0xffffffffu, s, o);
                if (lane == 0) red[w] = s;
                __syncthreads();
                s = red[0] + red[1];
                v2 *= (1.0f / s);
            }
            g_beta[t * BN + base] = v2;
            psh[t & 1][j] = v2 * e_t;   // carry beta_t * E_t to step t-1

            // rotate E pipeline: next step (t-1) uses E[t-1]
            e_t = (t >= 1) ? eb[(t - 1) & 3] : 0.0f;
            eb[(t - 1) & 3] = e_pref;
            __syncthreads();
        }
    }
}

// ---------------------------------------------------------------------------
// Kernel 3: gamma. g = log(alpha)+log(beta); out = g - LSE_j(g).
// Scales cancel. Tiled so output writes coalesce along t.
// grid (T/32, B), 256 threads.
// ---------------------------------------------------------------------------
__global__ void __launch_bounds__(256) gamma_kernel(float* __restrict__ out) {
    __shared__ float gsh[64][33];
    __shared__ float part[8][32];
    __shared__ float lse[32];

    int b   = blockIdx.y;
    int t0  = blockIdx.x * 32;
    int tid = threadIdx.x;
    int c   = tid & 63;   // j for load phase
    int r   = tid >> 6;   // 0..3

#pragma unroll
    for (int rep = 0; rep < 8; rep++) {
        int tt  = rep * 4 + r;
        int idx = (t0 + tt) * BN + b * NQ + c;
        gsh[c][tt] = __logf(g_alpha[idx]) + __logf(g_beta[idx]);
    }
    __syncthreads();

    int tt  = tid & 31;
    int seg = tid >> 5;   // 0..7, 8 j's each

    float m = -3.4e38f;
#pragma unroll
    for (int k = 0; k < 8; k++) m = fmaxf(m, gsh[seg * 8 + k][tt]);
    part[seg][tt] = m;
    __syncthreads();

    if (seg == 0) {
        float mm = part[0][tt];
#pragma unroll
        for (int k = 1; k < 8; k++) mm = fmaxf(mm, part[k][tt]);
        lse[tt] = mm;   // temporarily store the max
    }
    __syncthreads();

    float mm = lse[tt];
    float ss = 0.f;
#pragma unroll
    for (int k = 0; k < 8; k++) ss += __expf(gsh[seg * 8 + k][tt] - mm);
    part[seg][tt] = ss;
    __syncthreads();

    if (seg == 0) {
        float s = 0.f;
#pragma unroll
        for (int k = 0; k < 8; k++) s += part[k][tt];
        lse[tt] = mm + __logf(s);
    }
    __syncthreads();

    float l = lse[tt];
#pragma unroll
    for (int rep = 0; rep < 8; rep++) {
        int jj = rep * 8 + seg;
        out[b * NQ * TQ + jj * TQ + t0 + tt] = gsh[jj][tt] - l;
    }
}

// ---------------------------------------------------------------------------
extern "C" void kernel_launch(void* const* d_in, const int* in_sizes, int n_in,
                              void* d_out, int out_size) {
    const float* emissions = (const float*)d_in[0];   // [B, N, T]
    const float* init      = (const float*)d_in[1];   // [N]
    const float* trans     = (const float*)d_in[2];   // [N, N]
    float* out = (float*)d_out;                       // [B, N, T]

    expT_kernel<<<dim3(TQ / 64, BQ), 256>>>(emissions);
    scan_kernel<<<dim3(BQ, 2), 64>>>(trans, init);
    gamma_kernel<<<dim3(TQ / 32, BQ), 256>>>(out);
}

// round 4
// speedup vs baseline: 1.8082x; 1.8082x over previous
#include <cuda_runtime.h>

#define BQ 64
#define NQ 64
#define TQ 4096
#define BN (BQ * NQ)   // 4096 floats per time slice

// Scratch (module-load allocated): E = exp(emissions) in [t][b][j] layout,
// plus linear-domain alpha/beta (arbitrary per-(b,t) scale; cancels in gamma).
__device__ float g_E[TQ * BN];
__device__ float g_alpha[TQ * BN];
__device__ float g_beta[TQ * BN];

// ---------------------------------------------------------------------------
// Kernel 1: E[t][b][j] = exp(emissions[b][j][t])  (tiled transpose via shared)
// grid (T/64, B), 256 threads
// ---------------------------------------------------------------------------
__global__ void __launch_bounds__(256) expT_kernel(const float* __restrict__ em) {
    __shared__ float tile[64][65];
    int b  = blockIdx.y;
    int t0 = blockIdx.x * 64;
    int tid = threadIdx.x;
    int c  = tid & 63;
    int r4 = tid >> 6;

#pragma unroll
    for (int rep = 0; rep < 16; rep++) {
        int j = rep * 4 + r4;
        tile[j][c] = __expf(em[b * NQ * TQ + j * TQ + t0 + c]);
    }
    __syncthreads();
#pragma unroll
    for (int rep = 0; rep < 16; rep++) {
        int tt = rep * 4 + r4;
        g_E[(t0 + tt) * BN + b * NQ + c] = tile[c][tt];
    }
}

// ---------------------------------------------------------------------------
// Kernel 2: forward/backward linear-domain scans.
// grid (B, 2): blockIdx.x = batch, blockIdx.y = 0 fwd / 1 bwd. 64 threads.
// Thread j holds column j (fwd) or row j (bwd) of A in 64 registers.
// Renormalize by the vector sum every 8 steps (uniform scale cancels in gamma).
// E prefetch: 4 NAMED register slots, loops unrolled by 4 so slot selection is
// compile-time -> no local-memory spill, LDG wait lands 4 steps downstream.
// ---------------------------------------------------------------------------

// one forward step at time T consuming E register EREG (holds E[T]),
// then refilling EREG with E[T+4] (clamped)
#define FWD_STEP(T, EREG) {                                                    \
    float e_new = g_E[(((T) + 4 < TQ) ? (T) + 4 : TQ - 1) * BN + base];        \
    const float4* pv = (const float4*)&psh[((T) - 1) & 1][0];                  \
    float s0 = 0.f, s1 = 0.f, s2 = 0.f, s3 = 0.f;                              \
    _Pragma("unroll")                                                          \
    for (int k = 0; k < 16; k++) {                                             \
        float4 q = pv[k];                                                      \
        s0 = fmaf(q.x, A0[2 * k],     s0);                                     \
        s1 = fmaf(q.y, A1[2 * k],     s1);                                     \
        s2 = fmaf(q.z, A0[2 * k + 1], s2);                                     \
        s3 = fmaf(q.w, A1[2 * k + 1], s3);                                     \
    }                                                                          \
    float v2 = ((s0 + s1) + (s2 + s3)) * (EREG);                               \
    if (((T) & 7) == 7) {                                                      \
        float s = v2;                                                          \
        _Pragma("unroll")                                                      \
        for (int o = 16; o; o >>= 1) s += __shfl_xor_sync(0xffffffffu, s, o);  \
        if (lane == 0) red[w] = s;                                             \
        __syncthreads();                                                       \
        s = red[0] + red[1];                                                   \
        v2 *= (1.0f / s);                                                      \
    }                                                                          \
    psh[(T) & 1][j] = v2;                                                      \
    g_alpha[(T) * BN + base] = v2;                                             \
    __syncthreads();                                                           \
    (EREG) = e_new;                                                            \
}

// one backward step at time T consuming EREG (= E[T]); carry w_T = beta_T*E_T;
// refills EREG with E[T-4] (clamped)
#define BWD_STEP(T, EREG) {                                                    \
    float e_new = g_E[(((T) >= 4) ? (T) - 4 : 0) * BN + base];                 \
    const float4* pv = (const float4*)&psh[((T) + 1) & 1][0];                  \
    float s0 = 0.f, s1 = 0.f, s2 = 0.f, s3 = 0.f;                              \
    _Pragma("unroll")                                                          \
    for (int k = 0; k < 16; k++) {                                             \
        float4 q = pv[k];                                                      \
        s0 = fmaf(q.x, A0[2 * k],     s0);                                     \
        s1 = fmaf(q.y, A1[2 * k],     s1);                                     \
        s2 = fmaf(q.z, A0[2 * k + 1], s2);                                     \
        s3 = fmaf(q.w, A1[2 * k + 1], s3);                                     \
    }                                                                          \
    float v2 = (s0 + s1) + (s2 + s3);                                          \
    if (((T) & 7) == 0) {                                                      \
        float s = v2;                                                          \
        _Pragma("unroll")                                                      \
        for (int o = 16; o; o >>= 1) s += __shfl_xor_sync(0xffffffffu, s, o);  \
        if (lane == 0) red[w] = s;                                             \
        __syncthreads();                                                       \
        s = red[0] + red[1];                                                   \
        v2 *= (1.0f / s);                                                      \
    }                                                                          \
    g_beta[(T) * BN + base] = v2;                                              \
    psh[(T) & 1][j] = v2 * (EREG);                                             \
    __syncthreads();                                                           \
    (EREG) = e_new;                                                            \
}

__global__ void __launch_bounds__(64) scan_kernel(const float* __restrict__ trans,
                                                 const float* __restrict__ init) {
    const int b    = blockIdx.x;
    const int dir  = blockIdx.y;
    const int j    = threadIdx.x;
    const int lane = j & 31;
    const int w    = j >> 5;

    __shared__ __align__(16) float psh[2][64];
    __shared__ float red[2];

    float A0[32], A1[32];   // 64 matrix values per thread, split even/odd
    if (dir == 0) {
        // column j of A: A0[k] = A[2k][j], A1[k] = A[2k+1][j]
#pragma unroll
        for (int k = 0; k < 32; k++) {
            A0[k] = trans[(2 * k) * NQ + j];
            A1[k] = trans[(2 * k + 1) * NQ + j];
        }
    } else {
        // row j of A (contiguous)
        const float2* row = (const float2*)(trans + j * NQ);
#pragma unroll
        for (int k = 0; k < 32; k++) {
            float2 p = row[k];
            A0[k] = p.x;
            A1[k] = p.y;
        }
    }

    const int base = b * NQ + j;

    if (dir == 0) {
        // ---------------- forward ----------------
        float v = init[j] * g_E[0 * BN + base];
        {   // normalize at t=0
            float s = v;
#pragma unroll
            for (int o = 16; o; o >>= 1) s += __shfl_xor_sync(0xffffffffu, s, o);
            if (lane == 0) red[w] = s;
            __syncthreads();
            s = red[0] + red[1];
            v *= (1.0f / s);
        }
        psh[0][j] = v;
        g_alpha[0 * BN + base] = v;

        // prefill slots: e0..e3 hold E[1..4]
        float e0 = g_E[1 * BN + base];
        float e1 = g_E[2 * BN + base];
        float e2 = g_E[3 * BN + base];
        float e3 = g_E[4 * BN + base];
        __syncthreads();

        int t = 1;
        for (; t + 3 <= TQ - 1 - 3; t += 4) {   // main loop: t = 1 .. 4092
            FWD_STEP(t,     e0);
            FWD_STEP(t + 1, e1);
            FWD_STEP(t + 2, e2);
            FWD_STEP(t + 3, e3);
        }
        // tail: t = 4093, 4094, 4095 (slots line up: e0, e1, e2)
        FWD_STEP(t,     e0);
        FWD_STEP(t + 1, e1);
        FWD_STEP(t + 2, e2);
    } else {
        // ---------------- backward ----------------
        g_beta[(TQ - 1) * BN + base] = 1.0f;
        psh[(TQ - 1) & 1][j] = g_E[(TQ - 1) * BN + base];   // carry = beta*E at T-1

        // prefill slots: consumed at t = TQ-2, TQ-3, TQ-4, TQ-5
        float e0 = g_E[(TQ - 2) * BN + base];
        float e1 = g_E[(TQ - 3) * BN + base];
        float e2 = g_E[(TQ - 4) * BN + base];
        float e3 = g_E[(TQ - 5) * BN + base];
        __syncthreads();

        int t = TQ - 2;
        for (; t - 3 >= 3; t -= 4) {            // main loop: t = 4094 .. 6
            BWD_STEP(t,     e0);
            BWD_STEP(t - 1, e1);
            BWD_STEP(t - 2, e2);
            BWD_STEP(t - 3, e3);
        }
        // tail: t = 2, 1, 0 (slots line up: e0, e1, e2)
        BWD_STEP(t,     e0);
        BWD_STEP(t - 1, e1);
        BWD_STEP(t - 2, e2);
    }
}

// ---------------------------------------------------------------------------
// Kernel 3: gamma. g = log(alpha)+log(beta); out = g - LSE_j(g).
// Scales cancel. Tiled so output writes coalesce along t.
// grid (T/32, B), 256 threads.
// ---------------------------------------------------------------------------
__global__ void __launch_bounds__(256) gamma_kernel(float* __restrict__ out) {
    __shared__ float gsh[64][33];
    __shared__ float part[8][32];
    __shared__ float lse[32];

    int b   = blockIdx.y;
    int t0  = blockIdx.x * 32;
    int tid = threadIdx.x;
    int c   = tid & 63;
    int r   = tid >> 6;

#pragma unroll
    for (int rep = 0; rep < 8; rep++) {
        int tt  = rep * 4 + r;
        int idx = (t0 + tt) * BN + b * NQ + c;
        gsh[c][tt] = __logf(g_alpha[idx]) + __logf(g_beta[idx]);
    }
    __syncthreads();

    int tt  = tid & 31;
    int seg = tid >> 5;

    float m = -3.4e38f;
#pragma unroll
    for (int k = 0; k < 8; k++) m = fmaxf(m, gsh[seg * 8 + k][tt]);
    part[seg][tt] = m;
    __syncthreads();

    if (seg == 0) {
        float mm = part[0][tt];
#pragma unroll
        for (int k = 1; k < 8; k++) mm = fmaxf(mm, part[k][tt]);
        lse[tt] = mm;
    }
    __syncthreads();

    float mm = lse[tt];
    float ss = 0.f;
#pragma unroll
    for (int k = 0; k < 8; k++) ss += __expf(gsh[seg * 8 + k][tt] - mm);
    part[seg][tt] = ss;
    __syncthreads();

    if (seg == 0) {
        float s = 0.f;
#pragma unroll
        for (int k = 0; k < 8; k++) s += part[k][tt];
        lse[tt] = mm + __logf(s);
    }
    __syncthreads();

    float l = lse[tt];
#pragma unroll
    for (int rep = 0; rep < 8; rep++) {
        int jj = rep * 8 + seg;
        out[b * NQ * TQ + jj * TQ + t0 + tt] = gsh[jj][tt] - l;
    }
}

// ---------------------------------------------------------------------------
extern "C" void kernel_launch(void* const* d_in, const int* in_sizes, int n_in,
                              void* d_out, int out_size) {
    const float* emissions = (const float*)d_in[0];   // [B, N, T]
    const float* init      = (const float*)d_in[1];   // [N]
    const float* trans     = (const float*)d_in[2];   // [N, N]
    float* out = (float*)d_out;                       // [B, N, T]

    expT_kernel<<<dim3(TQ / 64, BQ), 256>>>(emissions);
    scan_kernel<<<dim3(BQ, 2), 64>>>(trans, init);
    gamma_kernel<<<dim3(TQ / 32, BQ), 256>>>(out);
}

// round 5
// speedup vs baseline: 2.9276x; 1.6190x over previous
#include <cuda_runtime.h>

#define BQ 64
#define NQ 64
#define TQ 4096
#define BN (BQ * NQ)   // 4096 floats per time slice

// Scratch (module-load allocated): E = exp(emissions) in [t][b][j] layout,
// plus linear-domain alpha/beta (arbitrary per-(b,t) scale; cancels in gamma).
__device__ float g_E[TQ * BN];
__device__ float g_alpha[TQ * BN];
__device__ float g_beta[TQ * BN];

// ---------------------------------------------------------------------------
// Kernel 1: E[t][b][j] = exp(emissions[b][j][t])  (tiled transpose via shared)
// ---------------------------------------------------------------------------
__global__ void __launch_bounds__(256) expT_kernel(const float* __restrict__ em) {
    __shared__ float tile[64][65];
    int b  = blockIdx.y;
    int t0 = blockIdx.x * 64;
    int tid = threadIdx.x;
    int c  = tid & 63;
    int r4 = tid >> 6;

#pragma unroll
    for (int rep = 0; rep < 16; rep++) {
        int j = rep * 4 + r4;
        tile[j][c] = __expf(em[b * NQ * TQ + j * TQ + t0 + c]);
    }
    __syncthreads();
#pragma unroll
    for (int rep = 0; rep < 16; rep++) {
        int tt = rep * 4 + r4;
        g_E[(t0 + tt) * BN + b * NQ + c] = tile[c][tt];
    }
}

// ---------------------------------------------------------------------------
// Kernel 2: forward/backward linear-domain scans.
// grid (B, 2), 128 threads. Thread pair (j = tid>>1, h = tid&1) splits state
// j's 64-term dot product in half (32 FFMA each), combined via shfl_xor(1).
// Renorm every 8 steps, PIPELINED: partial sums published at t%8==7(fwd)/0(bwd),
// the 1/s scale applied one step later (uniform scale cancels in gamma).
// E prefetch: 8 named register slots, distance 8, loops unrolled by 8.
// ---------------------------------------------------------------------------

#define DOT_HALF(PBUF)                                                         \
    const float4* pv = (const float4*)&psh[PBUF][h * 32];                      \
    float s0 = 0.f, s1 = 0.f, s2 = 0.f, s3 = 0.f;                              \
    _Pragma("unroll")                                                          \
    for (int k = 0; k < 8; k++) {                                              \
        float4 q = pv[k];                                                      \
        s0 = fmaf(q.x, Areg[4 * k],     s0);                                   \
        s1 = fmaf(q.y, Areg[4 * k + 1], s1);                                   \
        s2 = fmaf(q.z, Areg[4 * k + 2], s2);                                   \
        s3 = fmaf(q.w, Areg[4 * k + 3], s3);                                   \
    }                                                                          \
    float hf = (s0 + s1) + (s2 + s3);                                          \
    float v2 = hf + __shfl_xor_sync(0xffffffffu, hf, 1);

#define REDUCE_PUB()                                                           \
    {                                                                          \
        float s = v2;                                                          \
        s += __shfl_xor_sync(0xffffffffu, s, 2);                               \
        s += __shfl_xor_sync(0xffffffffu, s, 4);                               \
        s += __shfl_xor_sync(0xffffffffu, s, 8);                               \
        s += __shfl_xor_sync(0xffffffffu, s, 16);                              \
        if (lane == 0) red2[w] = s;                                            \
    }

// forward step at time T: consumes EREG = E[T]; refills EREG with E[T+8]
#define FWD_STEP(T, EREG, APPLY, REDUCE) do {                                  \
    float e_new = g_E[(((T) + 8 < TQ) ? (T) + 8 : TQ - 1) * BN + ebase];       \
    if (APPLY) {                                                               \
        float4 r4 = *(const float4*)red2;                                      \
        inv_s = __frcp_rn((r4.x + r4.y) + (r4.z + r4.w));                      \
    }                                                                          \
    DOT_HALF(((T) - 1) & 1)                                                    \
    if (APPLY) v2 *= inv_s;                                                    \
    v2 *= (EREG);                                                              \
    if (REDUCE) REDUCE_PUB()                                                   \
    if (h == 0) {                                                              \
        psh[(T) & 1][j] = v2;                                                  \
        g_alpha[(T) * BN + ebase] = v2;                                        \
    }                                                                          \
    __syncthreads();                                                           \
    (EREG) = e_new;                                                            \
} while (0)

// backward step at time T: EREG = E[T] feeds the carry; refills with E[T-8]
#define BWD_STEP(T, EREG, APPLY, REDUCE) do {                                  \
    float e_new = g_E[(((T) >= 8) ? (T) - 8 : 0) * BN + ebase];                \
    if (APPLY) {                                                               \
        float4 r4 = *(const float4*)red2;                                      \
        inv_s = __frcp_rn((r4.x + r4.y) + (r4.z + r4.w));                      \
    }                                                                          \
    DOT_HALF(((T) + 1) & 1)                                                    \
    if (APPLY) v2 *= inv_s;                                                    \
    if (REDUCE) REDUCE_PUB()                                                   \
    if (h == 0) {                                                              \
        g_beta[(T) * BN + ebase] = v2;                                         \
        psh[(T) & 1][j] = v2 * (EREG);                                         \
    }                                                                          \
    __syncthreads();                                                           \
    (EREG) = e_new;                                                            \
} while (0)

__global__ void __launch_bounds__(128) scan_kernel(const float* __restrict__ trans,
                                                   const float* __restrict__ init) {
    const int b    = blockIdx.x;
    const int dir  = blockIdx.y;
    const int tid  = threadIdx.x;
    const int j    = tid >> 1;   // state index 0..63
    const int h    = tid & 1;    // which half of the dot
    const int lane = tid & 31;
    const int w    = tid >> 5;

    __shared__ __align__(16) float psh[2][64];
    __shared__ __align__(16) float red2[4];

    // per-thread half-row/column of A
    float Areg[32];
    if (dir == 0) {
        // fwd needs A[i][j], i in [32h, 32h+32)
#pragma unroll
        for (int m = 0; m < 32; m++)
            Areg[m] = trans[(32 * h + m) * NQ + j];
    } else {
        // bwd needs A[j][i], i in [32h, 32h+32)  (contiguous)
        const float4* rp = (const float4*)(trans + j * NQ + 32 * h);
#pragma unroll
        for (int k = 0; k < 8; k++) {
            float4 a = rp[k];
            Areg[4 * k] = a.x; Areg[4 * k + 1] = a.y;
            Areg[4 * k + 2] = a.z; Areg[4 * k + 3] = a.w;
        }
    }

    const int ebase = b * NQ + j;
    float inv_s = 1.0f;

    if (dir == 0) {
        // ---------------- forward ----------------
        // t = 0 (no normalization needed; first renorm covers the range)
        float v0 = init[j] * g_E[0 * BN + ebase];
        if (h == 0) {
            psh[0][j] = v0;
            g_alpha[0 * BN + ebase] = v0;
        }
        // prefill E slots with E[1..8]
        float e0 = g_E[1 * BN + ebase], e1 = g_E[2 * BN + ebase];
        float e2 = g_E[3 * BN + ebase], e3 = g_E[4 * BN + ebase];
        float e4 = g_E[5 * BN + ebase], e5 = g_E[6 * BN + ebase];
        float e6 = g_E[7 * BN + ebase], e7 = g_E[8 * BN + ebase];
        __syncthreads();

        // prologue t = 1..8 (renorm measured at 7, applied at 8)
        FWD_STEP(1, e0, 0, 0); FWD_STEP(2, e1, 0, 0);
        FWD_STEP(3, e2, 0, 0); FWD_STEP(4, e3, 0, 0);
        FWD_STEP(5, e4, 0, 0); FWD_STEP(6, e5, 0, 0);
        FWD_STEP(7, e6, 0, 1); FWD_STEP(8, e7, 1, 0);

        // main: t0 = 9, 17, ..., 4081  (510 iterations, covers 9..4088)
        for (int t0 = 9; t0 <= TQ - 15; t0 += 8) {
            FWD_STEP(t0,     e0, 0, 0); FWD_STEP(t0 + 1, e1, 0, 0);
            FWD_STEP(t0 + 2, e2, 0, 0); FWD_STEP(t0 + 3, e3, 0, 0);
            FWD_STEP(t0 + 4, e4, 0, 0); FWD_STEP(t0 + 5, e5, 0, 0);
            FWD_STEP(t0 + 6, e6, 0, 1); FWD_STEP(t0 + 7, e7, 1, 0);
        }

        // epilogue t = 4089..4095 (no renorm needed)
        FWD_STEP(TQ - 7, e0, 0, 0); FWD_STEP(TQ - 6, e1, 0, 0);
        FWD_STEP(TQ - 5, e2, 0, 0); FWD_STEP(TQ - 4, e3, 0, 0);
        FWD_STEP(TQ - 3, e4, 0, 0); FWD_STEP(TQ - 2, e5, 0, 0);
        FWD_STEP(TQ - 1, e6, 0, 0);
    } else {
        // ---------------- backward ----------------
        float eT = g_E[(TQ - 1) * BN + ebase];
        if (h == 0) {
            g_beta[(TQ - 1) * BN + ebase] = 1.0f;
            psh[(TQ - 1) & 1][j] = eT;   // carry = beta_{T-1} * E_{T-1}
        }
        // prefill E slots with E[4094..4087]
        float e0 = g_E[(TQ - 2) * BN + ebase], e1 = g_E[(TQ - 3) * BN + ebase];
        float e2 = g_E[(TQ - 4) * BN + ebase], e3 = g_E[(TQ - 5) * BN + ebase];
        float e4 = g_E[(TQ - 6) * BN + ebase], e5 = g_E[(TQ - 7) * BN + ebase];
        float e6 = g_E[(TQ - 8) * BN + ebase], e7 = g_E[(TQ - 9) * BN + ebase];
        __syncthreads();

        // prologue t = 4094..4087 (renorm measured at 4088, applied at 4087)
        BWD_STEP(TQ - 2, e0, 0, 0); BWD_STEP(TQ - 3, e1, 0, 0);
        BWD_STEP(TQ - 4, e2, 0, 0); BWD_STEP(TQ - 5, e3, 0, 0);
        BWD_STEP(TQ - 6, e4, 0, 0); BWD_STEP(TQ - 7, e5, 0, 0);
        BWD_STEP(TQ - 8, e6, 0, 1); BWD_STEP(TQ - 9, e7, 1, 0);

        // main: t0 = 4086 down to 14 (510 iterations, covers 4086..7)
        for (int t0 = TQ - 10; t0 >= 14; t0 -= 8) {
            BWD_STEP(t0,     e0, 0, 0); BWD_STEP(t0 - 1, e1, 0, 0);
            BWD_STEP(t0 - 2, e2, 0, 0); BWD_STEP(t0 - 3, e3, 0, 0);
            BWD_STEP(t0 - 4, e4, 0, 0); BWD_STEP(t0 - 5, e5, 0, 0);
            BWD_STEP(t0 - 6, e6, 0, 1); BWD_STEP(t0 - 7, e7, 1, 0);
        }

        // epilogue t = 6..0
        BWD_STEP(6, e0, 0, 0); BWD_STEP(5, e1, 0, 0);
        BWD_STEP(4, e2, 0, 0); BWD_STEP(3, e3, 0, 0);
        BWD_STEP(2, e4, 0, 0); BWD_STEP(1, e5, 0, 0);
        BWD_STEP(0, e6, 0, 0);
    }
}

// ---------------------------------------------------------------------------
// Kernel 3: gamma. g = log(alpha)+log(beta); out = g - LSE_j(g).
// Scales cancel. Tiled so output writes coalesce along t.
// ---------------------------------------------------------------------------
__global__ void __launch_bounds__(256) gamma_kernel(float* __restrict__ out) {
    __shared__ float gsh[64][33];
    __shared__ float part[8][32];
    __shared__ float lse[32];

    int b   = blockIdx.y;
    int t0  = blockIdx.x * 32;
    int tid = threadIdx.x;
    int c   = tid & 63;
    int r   = tid >> 6;

#pragma unroll
    for (int rep = 0; rep < 8; rep++) {
        int tt  = rep * 4 + r;
        int idx = (t0 + tt) * BN + b * NQ + c;
        gsh[c][tt] = __logf(g_alpha[idx]) + __logf(g_beta[idx]);
    }
    __syncthreads();

    int tt  = tid & 31;
    int seg = tid >> 5;

    float m = -3.4e38f;
#pragma unroll
    for (int k = 0; k < 8; k++) m = fmaxf(m, gsh[seg * 8 + k][tt]);
    part[seg][tt] = m;
    __syncthreads();

    if (seg == 0) {
        float mm = part[0][tt];
#pragma unroll
        for (int k = 1; k < 8; k++) mm = fmaxf(mm, part[k][tt]);
        lse[tt] = mm;
    }
    __syncthreads();

    float mm = lse[tt];
    float ss = 0.f;
#pragma unroll
    for (int k = 0; k < 8; k++) ss += __expf(gsh[seg * 8 + k][tt] - mm);
    part[seg][tt] = ss;
    __syncthreads();

    if (seg == 0) {
        float s = 0.f;
#pragma unroll
        for (int k = 0; k < 8; k++) s += part[k][tt];
        lse[tt] = mm + __logf(s);
    }
    __syncthreads();

    float l = lse[tt];
#pragma unroll
    for (int rep = 0; rep < 8; rep++) {
        int jj = rep * 8 + seg;
        out[b * NQ * TQ + jj * TQ + t0 + tt] = gsh[jj][tt] - l;
    }
}

// ---------------------------------------------------------------------------
extern "C" void kernel_launch(void* const* d_in, const int* in_sizes, int n_in,
                              void* d_out, int out_size) {
    const float* emissions = (const float*)d_in[0];   // [B, N, T]
    const float* init      = (const float*)d_in[1];   // [N]
    const float* trans     = (const float*)d_in[2];   // [N, N]
    float* out = (float*)d_out;                       // [B, N, T]

    expT_kernel<<<dim3(TQ / 64, BQ), 256>>>(emissions);
    scan_kernel<<<dim3(BQ, 2), 128>>>(trans, init);
    gamma_kernel<<<dim3(TQ / 32, BQ), 256>>>(out);
}